// round 13
// baseline (speedup 1.0000x reference)
#include <cuda_runtime.h>
#include <cstdint>

#define L       8192
#define CHN     16
#define BATCH   32
#define NSTEPS  100
#define HSTEP   0.01f
#define TILEX   512
#define NTHR    128

typedef unsigned long long ull;

__device__ float g_z [(size_t)BATCH * CHN * L];
__device__ float g_k1[(size_t)BATCH * CHN * L];
__device__ float g_k2[(size_t)BATCH * CHN * L];

__device__ __forceinline__ ull pk2(float lo, float hi) {
    ull r; asm("mov.b64 %0, {%1,%2};" : "=l"(r) : "f"(lo), "f"(hi)); return r;
}
__device__ __forceinline__ void upk2(ull a, float& lo, float& hi) {
    asm("mov.b64 {%0,%1}, %2;" : "=f"(lo), "=f"(hi) : "l"(a));
}
__device__ __forceinline__ void fma2(ull &acc, ull a, ull b) {
    asm("fma.rn.f32x2 %0, %1, %2, %0;" : "+l"(acc) : "l"(a), "l"(b));
}

// Store one 4-wide output chunk with ghost-cell handling.
// Interior formula valid for x in [10, 8181]; ghosts replicate those edges.
__device__ __forceinline__ void store_chunk(float* __restrict__ orow, int x,
                                            float f0, float f1, float f2, float f3) {
    if (x >= 12 && x <= 8176) {
        *(float4*)(orow + x) = make_float4(f0, f1, f2, f3);
    } else if (x == 8) {
        #pragma unroll
        for (int i = 0; i < 10; ++i) orow[i] = f2;
        orow[10] = f2; orow[11] = f3;
    } else if (x == 8180) {
        orow[8180] = f0; orow[8181] = f1;
        #pragma unroll
        for (int i = 0; i < 10; ++i) orow[8182 + i] = f1;
    }
}

// STAGE 1: out = B(z + h conv(z))
// STAGE 2: out = B(0.75 z + 0.25 k + 0.25 h conv(k))
// STAGE 3: out = B(z/3 + 2k/3 + (2h/3) conv(k))
template<int STAGE>
__global__ void __launch_bounds__(NTHR, 4)
stage_k(const float* __restrict__ zin, const float* __restrict__ kin,
        float* __restrict__ out, const float* __restrict__ Wg)
{
    // wd[ci][co][12] : [w0,w0,w1,w1][w2,w2,w3,w3][w4,w4,-,-]
    __shared__ float wd[CHN * CHN * 12];
    const int tid = threadIdx.x;
    for (int i = tid; i < CHN * CHN * 5; i += NTHR) {
        int co = i / 80, r = i % 80, ci = r / 5, t = r % 5;
        float w = Wg[i];
        int base = (ci * 16 + co) * 12;
        wd[base + 2 * t]     = w;
        wd[base + 2 * t + 1] = w;
    }
    __syncthreads();

    const int lane = tid & 31;
    const int w    = tid >> 5;             // 4 warps
    const int coo  = (w & 1) * 8;          // cout base (0 or 8)
    const int sp   = w >> 1;               // segment pair 0/1
    const int ci0  = (w & 3) * 4;          // per-warp ci phase stagger
    const int b    = blockIdx.y;
    const int X0   = blockIdx.x * TILEX;

    const int xA = X0 + sp * 128 + 4 * lane;   // segment A chunk
    const int xB = xA + 256;                   // segment B chunk

    const int aA0 = (xA - 4 < 0) ? 0 : xA - 4;
    const int aB2 = (xB + 4 > L - 4) ? L - 4 : xB + 4;

    const float* csrc = (STAGE == 1 ? zin : kin) + (size_t)b * CHN * L;

    ull acc[8][4];   // acc[q][p]: lo = out[coo+q][xA+p], hi = out[coo+q][xB+p]
    #pragma unroll
    for (int q = 0; q < 8; ++q)
        #pragma unroll
        for (int j = 0; j < 4; ++j) acc[q][j] = 0ull;

    const float* rowp = csrc + (size_t)ci0 * L;
    const float* wrow = &wd[(ci0 * 16 + coo) * 12];
    int cp = ci0;

    #pragma unroll 1
    for (int it = 0; it < CHN; ++it) {
        float4 cA0 = *(const float4*)(rowp + aA0);
        float4 cA1 = *(const float4*)(rowp + xA);
        float4 cA2 = *(const float4*)(rowp + xA + 4);
        float4 cB0 = *(const float4*)(rowp + xB - 4);
        float4 cB1 = *(const float4*)(rowp + xB);
        float4 cB2 = *(const float4*)(rowp + aB2);

        // strided pairs: P[j] = (vA[xA-2+j], vB[xB-2+j]); each value used once
        ull P0 = pk2(cA0.z, cB0.z), P1 = pk2(cA0.w, cB0.w);
        ull P2 = pk2(cA1.x, cB1.x), P3 = pk2(cA1.y, cB1.y);
        ull P4 = pk2(cA1.z, cB1.z), P5 = pk2(cA1.w, cB1.w);
        ull P6 = pk2(cA2.x, cB2.x), P7 = pk2(cA2.y, cB2.y);

        #pragma unroll
        for (int q = 0; q < 8; ++q) {
            ulonglong2 u01 = *(const ulonglong2*)(wrow + q * 12);
            ulonglong2 u23 = *(const ulonglong2*)(wrow + q * 12 + 4);
            ull W4 = *(const ull*)(wrow + q * 12 + 8);
            ull W0 = u01.x, W1 = u01.y, W2 = u23.x, W3 = u23.y;

            fma2(acc[q][0], P0, W0); fma2(acc[q][0], P1, W1);
            fma2(acc[q][0], P2, W2); fma2(acc[q][0], P3, W3);
            fma2(acc[q][0], P4, W4);
            fma2(acc[q][1], P1, W0); fma2(acc[q][1], P2, W1);
            fma2(acc[q][1], P3, W2); fma2(acc[q][1], P4, W3);
            fma2(acc[q][1], P5, W4);
            fma2(acc[q][2], P2, W0); fma2(acc[q][2], P3, W1);
            fma2(acc[q][2], P4, W2); fma2(acc[q][2], P5, W3);
            fma2(acc[q][2], P6, W4);
            fma2(acc[q][3], P3, W0); fma2(acc[q][3], P4, W1);
            fma2(acc[q][3], P5, W2); fma2(acc[q][3], P6, W3);
            fma2(acc[q][3], P7, W4);
        }

        // advance ci with wrap (per-warp phase stagger)
        ++cp;
        if (cp == CHN) {
            cp = 0;
            rowp = csrc;
            wrow = &wd[coo * 12];
        } else {
            rowp += L;
            wrow += 16 * 12;
        }
    }

    // ---- epilogue ----
    const float ca = (STAGE == 1) ? 1.0f  : (STAGE == 2) ? 0.75f         : (1.0f / 3.0f);
    const float cb = (STAGE == 1) ? 0.0f  : (STAGE == 2) ? 0.25f         : (2.0f / 3.0f);
    const float cc = (STAGE == 1) ? HSTEP : (STAGE == 2) ? 0.25f * HSTEP : (2.0f * HSTEP / 3.0f);

    const float* zb = zin + (size_t)b * CHN * L;
    const float* kb = (STAGE == 1) ? nullptr : kin + (size_t)b * CHN * L;
    float*       ob = out + (size_t)b * CHN * L;

    #pragma unroll
    for (int q = 0; q < 8; ++q) {
        const int co = coo + q;
        const float* zrow = zb + (size_t)co * L;
        float*       orow = ob + (size_t)co * L;

        float cvA[4], cvB[4];
        #pragma unroll
        for (int p = 0; p < 4; ++p) upk2(acc[q][p], cvA[p], cvB[p]);

        #pragma unroll
        for (int s = 0; s < 2; ++s) {
            const int x = (s == 0) ? xA : xB;
            const float* cv = (s == 0) ? cvA : cvB;

            float4 zv = *(const float4*)(zrow + x);
            float r0, r1, r2, r3;
            if (STAGE == 1) {
                r0 = fmaf(cc, cv[0], zv.x); r1 = fmaf(cc, cv[1], zv.y);
                r2 = fmaf(cc, cv[2], zv.z); r3 = fmaf(cc, cv[3], zv.w);
            } else {
                float4 kv = *(const float4*)(kb + (size_t)co * L + x);
                r0 = fmaf(ca, zv.x, fmaf(cb, kv.x, cc * cv[0]));
                r1 = fmaf(ca, zv.y, fmaf(cb, kv.y, cc * cv[1]));
                r2 = fmaf(ca, zv.z, fmaf(cb, kv.z, cc * cv[2]));
                r3 = fmaf(ca, zv.w, fmaf(cb, kv.w, cc * cv[3]));
            }
            store_chunk(orow, x, r0, r1, r2, r3);
        }
    }
}

extern "C" void kernel_launch(void* const* d_in, const int* in_sizes, int n_in,
                              void* d_out, int out_size) {
    const float* z0 = (const float*)d_in[0];
    const float* W  = (const float*)d_in[1];
    float* out = (float*)d_out;

    float *zscr, *k1, *k2;
    cudaGetSymbolAddress((void**)&zscr, g_z);
    cudaGetSymbolAddress((void**)&k1,   g_k1);
    cudaGetSymbolAddress((void**)&k2,   g_k2);

    dim3 grid(L / TILEX, BATCH);   // (16, 32) = 512 CTAs of 128 threads
    for (int s = 0; s < NSTEPS; ++s) {
        const float* src;
        float* dst;
        if (s == 0)      { src = z0;   dst = zscr; }
        else if (s & 1)  { src = zscr; dst = out;  }
        else             { src = out;  dst = zscr; }

        stage_k<1><<<grid, NTHR>>>(src, src, k1, W);
        stage_k<2><<<grid, NTHR>>>(src, k1,  k2, W);
        stage_k<3><<<grid, NTHR>>>(src, k2,  dst, W);
    }
}

// round 14
// speedup vs baseline: 1.4973x; 1.4973x over previous
#include <cuda_runtime.h>
#include <cstdint>

#define L       8192
#define CHN     16
#define BATCH   32
#define NSTEPS  100
#define HSTEP   0.01f
#define TILEX   512
#define NTHR    128
#define PROW    272          // pair-row stride (pairs); 272*8B = 2176B = 17*128B

typedef unsigned int u32;
typedef unsigned long long ull;

__device__ float g_z [(size_t)BATCH * CHN * L];
__device__ float g_k1[(size_t)BATCH * CHN * L];
__device__ float g_k2[(size_t)BATCH * CHN * L];

__device__ __forceinline__ void upk2(ull a, float& lo, float& hi) {
    asm("mov.b64 {%0,%1}, %2;" : "=f"(lo), "=f"(hi) : "l"(a));
}
__device__ __forceinline__ void fma2(ull &acc, ull a, ull b) {
    asm("fma.rn.f32x2 %0, %1, %2, %0;" : "+l"(acc) : "l"(a), "l"(b));
}

// Store one 4-wide output chunk with ghost-cell handling.
// Interior formula valid for x in [10, 8181]; ghosts replicate those edges.
__device__ __forceinline__ void store_chunk(float* __restrict__ orow, int x,
                                            float f0, float f1, float f2, float f3) {
    if (x >= 12 && x <= 8176) {
        *(float4*)(orow + x) = make_float4(f0, f1, f2, f3);
    } else if (x == 8) {
        #pragma unroll
        for (int i = 0; i < 10; ++i) orow[i] = f2;
        orow[10] = f2; orow[11] = f3;
    } else if (x == 8180) {
        orow[8180] = f0; orow[8181] = f1;
        #pragma unroll
        for (int i = 0; i < 10; ++i) orow[8182 + i] = f1;
    }
}

// STAGE 1: out = B(z + h conv(z))
// STAGE 2: out = B(0.75 z + 0.25 k + 0.25 h conv(k))
// STAGE 3: out = B(z/3 + 2k/3 + (2h/3) conv(k))
template<int STAGE>
__global__ void __launch_bounds__(NTHR, 4)
stage_k(const float* __restrict__ zin, const float* __restrict__ kin,
        float* __restrict__ out, const float* __restrict__ Wg)
{
    extern __shared__ float sm[];
    ull*   pr = (ull*)sm;                      // 16 * PROW pairs (lo=x, hi=x+256)
    float* wd = sm + CHN * PROW * 2;           // 16*16*12 duplicated weights

    const int tid = threadIdx.x;
    const int b   = blockIdx.y;
    const int X0  = blockIdx.x * TILEX;

    // ---- weights: wd[ci][co][12] = [w0,w0,w1,w1][w2,w2,w3,w3][w4,w4,-,-]
    for (int i = tid; i < CHN * CHN * 5; i += NTHR) {
        int co = i / 80, r = i % 80, ci = r / 5, t = r % 5;
        float w = Wg[i];
        int base = (ci * 16 + co) * 12;
        wd[base + 2 * t]     = w;
        wd[base + 2 * t + 1] = w;
    }

    // ---- stage pre-paired input: pair j of row ci = (src[X0-4+j], src[X0+252+j])
    const float* csrc = (STAGE == 1 ? zin : kin) + (size_t)b * CHN * L;
    {
        const int ci  = tid >> 3;        // 16 rows
        const int sub = tid & 7;
        const float* crow = csrc + (size_t)ci * L;
        ull* prow = pr + ci * PROW;
        #pragma unroll
        for (int p4 = sub; p4 < 67; p4 += 8) {   // 67 groups of 4 pairs (268 pairs)
            int gx  = X0 - 4 + 4 * p4;
            int glo = gx < 0 ? 0 : gx;                       // clamp corrupts only ghosts
            int ghi = (gx + 256 > L - 4) ? L - 4 : gx + 256;
            float4 lo = *(const float4*)(crow + glo);
            float4 hi = *(const float4*)(crow + ghi);
            *(float4*)(prow + 4 * p4)     = make_float4(lo.x, hi.x, lo.y, hi.y);
            *(float4*)(prow + 4 * p4 + 2) = make_float4(lo.z, hi.z, lo.w, hi.w);
        }
    }
    __syncthreads();

    const int lane = tid & 31;
    const int w    = tid >> 5;             // 4 warps
    const int coo  = (w & 1) * 8;          // cout base (0 or 8)
    const int sp   = w >> 1;               // segment pair 0/1
    const int xA   = X0 + sp * 128 + 4 * lane;
    const int xB   = xA + 256;

    ull acc[8][4];   // acc[q][p]: lo = out[coo+q][xA+p], hi = out[coo+q][xB+p]
    #pragma unroll
    for (int q = 0; q < 8; ++q)
        #pragma unroll
        for (int j = 0; j < 4; ++j) acc[q][j] = 0ull;

    // window pair base: x = xA-2 -> j = sp*128 + 4*lane + 2 (even -> 16B aligned)
    const ull* pbase = pr + sp * 128 + 4 * lane + 2;
    const float* wrow0 = &wd[coo * 12];

    #pragma unroll 1
    for (int ci = 0; ci < CHN; ++ci) {
        ulonglong2 v01 = *(const ulonglong2*)(pbase + 0);
        ulonglong2 v23 = *(const ulonglong2*)(pbase + 2);
        ulonglong2 v45 = *(const ulonglong2*)(pbase + 4);
        ulonglong2 v67 = *(const ulonglong2*)(pbase + 6);
        ull P0 = v01.x, P1 = v01.y, P2 = v23.x, P3 = v23.y;
        ull P4 = v45.x, P5 = v45.y, P6 = v67.x, P7 = v67.y;

        const float* wrow = wrow0 + ci * (16 * 12);
        #pragma unroll
        for (int q = 0; q < 8; ++q) {
            ulonglong2 u01 = *(const ulonglong2*)(wrow + q * 12);
            ulonglong2 u23 = *(const ulonglong2*)(wrow + q * 12 + 4);
            ull W4 = *(const ull*)(wrow + q * 12 + 8);
            ull W0 = u01.x, W1 = u01.y, W2 = u23.x, W3 = u23.y;

            fma2(acc[q][0], P0, W0); fma2(acc[q][0], P1, W1);
            fma2(acc[q][0], P2, W2); fma2(acc[q][0], P3, W3);
            fma2(acc[q][0], P4, W4);
            fma2(acc[q][1], P1, W0); fma2(acc[q][1], P2, W1);
            fma2(acc[q][1], P3, W2); fma2(acc[q][1], P4, W3);
            fma2(acc[q][1], P5, W4);
            fma2(acc[q][2], P2, W0); fma2(acc[q][2], P3, W1);
            fma2(acc[q][2], P4, W2); fma2(acc[q][2], P5, W3);
            fma2(acc[q][2], P6, W4);
            fma2(acc[q][3], P3, W0); fma2(acc[q][3], P4, W1);
            fma2(acc[q][3], P5, W2); fma2(acc[q][3], P6, W3);
            fma2(acc[q][3], P7, W4);
        }
        pbase += PROW;
    }

    // ---- epilogue ----
    const float ca = (STAGE == 1) ? 1.0f  : (STAGE == 2) ? 0.75f         : (1.0f / 3.0f);
    const float cb = (STAGE == 1) ? 0.0f  : (STAGE == 2) ? 0.25f         : (2.0f / 3.0f);
    const float cc = (STAGE == 1) ? HSTEP : (STAGE == 2) ? 0.25f * HSTEP : (2.0f * HSTEP / 3.0f);

    const float* zb = zin + (size_t)b * CHN * L;
    float*       ob = out + (size_t)b * CHN * L;

    #pragma unroll
    for (int q = 0; q < 8; ++q) {
        const int co = coo + q;
        float* orow = ob + (size_t)co * L;

        // staged conv-source pairs for this co at the output chunk (j = xA - X0 + 4)
        const ull* kp = pr + co * PROW + sp * 128 + 4 * lane + 4;
        ulonglong2 k01 = *(const ulonglong2*)(kp);
        ulonglong2 k23 = *(const ulonglong2*)(kp + 2);

        float cvA[4], cvB[4], svA[4], svB[4];
        #pragma unroll
        for (int p = 0; p < 4; ++p) upk2(acc[q][p], cvA[p], cvB[p]);
        upk2(k01.x, svA[0], svB[0]); upk2(k01.y, svA[1], svB[1]);
        upk2(k23.x, svA[2], svB[2]); upk2(k23.y, svA[3], svB[3]);

        #pragma unroll
        for (int s = 0; s < 2; ++s) {
            const int x = (s == 0) ? xA : xB;
            const float* cv = (s == 0) ? cvA : cvB;
            const float* sv = (s == 0) ? svA : svB;   // staged source value (z for st1, k for st2/3)

            float r0, r1, r2, r3;
            if (STAGE == 1) {
                r0 = fmaf(cc, cv[0], sv[0]); r1 = fmaf(cc, cv[1], sv[1]);
                r2 = fmaf(cc, cv[2], sv[2]); r3 = fmaf(cc, cv[3], sv[3]);
            } else {
                const float* zrow = zb + (size_t)co * L;
                float4 zv = *(const float4*)(zrow + x);
                r0 = fmaf(ca, zv.x, fmaf(cb, sv[0], cc * cv[0]));
                r1 = fmaf(ca, zv.y, fmaf(cb, sv[1], cc * cv[1]));
                r2 = fmaf(ca, zv.z, fmaf(cb, sv[2], cc * cv[2]));
                r3 = fmaf(ca, zv.w, fmaf(cb, sv[3], cc * cv[3]));
            }
            store_chunk(orow, x, r0, r1, r2, r3);
        }
    }
}

extern "C" void kernel_launch(void* const* d_in, const int* in_sizes, int n_in,
                              void* d_out, int out_size) {
    const float* z0 = (const float*)d_in[0];
    const float* W  = (const float*)d_in[1];
    float* out = (float*)d_out;

    float *zscr, *k1, *k2;
    cudaGetSymbolAddress((void**)&zscr, g_z);
    cudaGetSymbolAddress((void**)&k1,   g_k1);
    cudaGetSymbolAddress((void**)&k2,   g_k2);

    const size_t smem_bytes =
        (size_t)(CHN * PROW * 2 + CHN * CHN * 12) * sizeof(float);   // 34816 + 12288 = 47104
    dim3 grid(L / TILEX, BATCH);   // (16, 32) = 512 CTAs of 128 threads
    for (int s = 0; s < NSTEPS; ++s) {
        const float* src;
        float* dst;
        if (s == 0)      { src = z0;   dst = zscr; }
        else if (s & 1)  { src = zscr; dst = out;  }
        else             { src = out;  dst = zscr; }

        stage_k<1><<<grid, NTHR, smem_bytes>>>(src, src, k1, W);
        stage_k<2><<<grid, NTHR, smem_bytes>>>(src, k1,  k2, W);
        stage_k<3><<<grid, NTHR, smem_bytes>>>(src, k2,  dst, W);
    }
}